// round 11
// baseline (speedup 1.0000x reference)
#include <cuda_runtime.h>
#include <cuda_bf16.h>
#include <cstdint>
#include <cstddef>

// Problem constants
#define BATCH   8
#define SEQ     1024
#define CEMB    1024
#define NHEAD   16
#define HDIM    64
#define NQS     4
#define MROWS   (BATCH * SEQ)          // 8192
#define QKV_N   ((NQS + 2) * CEMB)     // 6144
#define CAT_N   (NQS * CEMB)           // 4096

// Scratch (allocation-free rule: __device__ globals)
__device__ float g_qkv [(size_t)MROWS * QKV_N];   // [8192,6144] fp32
__device__ float g_ycat[(size_t)MROWS * CAT_N];   // [8192,4096] fp32
__device__ __nv_bfloat16 g_xhi [(size_t)MROWS * CEMB];
__device__ __nv_bfloat16 g_xlo [(size_t)MROWS * CEMB];
__device__ __nv_bfloat16 g_wahi[(size_t)QKV_N * CEMB];
__device__ __nv_bfloat16 g_walo[(size_t)QKV_N * CEMB];
__device__ __nv_bfloat16 g_ychi[(size_t)MROWS * CAT_N];
__device__ __nv_bfloat16 g_yclo[(size_t)MROWS * CAT_N];
__device__ __nv_bfloat16 g_wphi[(size_t)CEMB * CAT_N];
__device__ __nv_bfloat16 g_wplo[(size_t)CEMB * CAT_N];

// ---------------------------------------------------------------------------
// helpers
// ---------------------------------------------------------------------------
__device__ __forceinline__ uint32_t smem_u32(const void* p) {
    uint32_t a;
    asm("{ .reg .u64 t; cvta.to.shared.u64 t, %1; cvt.u32.u64 %0, t; }"
        : "=r"(a) : "l"(p));
    return a;
}
__device__ __forceinline__ void cp16(uint32_t dst, const void* src) {
    asm volatile("cp.async.cg.shared.global [%0], [%1], 16;" :: "r"(dst), "l"(src) : "memory");
}
#define CP_COMMIT() asm volatile("cp.async.commit_group;" ::: "memory")
#define CP_WAIT(n)  asm volatile("cp.async.wait_group %0;" :: "n"(n) : "memory")

#define LDSM_X4(r0, r1, r2, r3, addr)                                          \
    asm volatile("ldmatrix.sync.aligned.m8n8.x4.shared.b16 {%0,%1,%2,%3}, [%4];" \
                 : "=r"(r0), "=r"(r1), "=r"(r2), "=r"(r3) : "r"(addr))

#define MMA_BF16(d, a, b0, b1)                                                 \
    asm volatile("mma.sync.aligned.m16n8k16.row.col.f32.bf16.bf16.f32 "        \
                 "{%0,%1,%2,%3}, {%4,%5,%6,%7}, {%8,%9}, {%0,%1,%2,%3};"       \
                 : "+f"((d)[0]), "+f"((d)[1]), "+f"((d)[2]), "+f"((d)[3])      \
                 : "r"((a)[0]), "r"((a)[1]), "r"((a)[2]), "r"((a)[3]),         \
                   "r"(b0), "r"(b1))

__device__ __forceinline__ void store_hilo2(float a, float b,
                                            __nv_bfloat16* hi, __nv_bfloat16* lo) {
    __nv_bfloat162 hv, lv;
    hv.x = __float2bfloat16(a); hv.y = __float2bfloat16(b);
    lv.x = __float2bfloat16(a - __bfloat162float(hv.x));
    lv.y = __float2bfloat16(b - __bfloat162float(hv.y));
    *(__nv_bfloat162*)hi = hv;
    *(__nv_bfloat162*)lo = lv;
}

// ---------------------------------------------------------------------------
// fp32 -> bf16 hi/lo split
// ---------------------------------------------------------------------------
__global__ __launch_bounds__(256)
void cvt_hilo(const float* __restrict__ s, __nv_bfloat16* __restrict__ hi,
              __nv_bfloat16* __restrict__ lo, size_t n4)
{
    size_t i = (size_t)blockIdx.x * blockDim.x + threadIdx.x;
    if (i >= n4) return;
    float4 v = ((const float4*)s)[i];
    store_hilo2(v.x, v.y, hi + 4 * i, lo + 4 * i);
    store_hilo2(v.z, v.w, hi + 4 * i + 2, lo + 4 * i + 2);
}

// ---------------------------------------------------------------------------
// C[M,N] = A[M,K] @ B[N,K]^T via mma.sync bf16, 3-pass hi/lo split.
// CTA tile 128x128, BK=32, cp.async double buffer, 8 warps of 32x64.
// EXACT R3-proven kernel (fp32 C output).
// ---------------------------------------------------------------------------
#define BK        32
#define TPAD      40
#define TILE_B    (128 * TPAD * 2)
#define STAGE_B   (4 * TILE_B)
#define GEMM_SMEM (2 * STAGE_B)

__global__ __launch_bounds__(256, 1)
void gemm_bf16x3(const __nv_bfloat16* __restrict__ Ahi, const __nv_bfloat16* __restrict__ Alo,
                 const __nv_bfloat16* __restrict__ Bhi, const __nv_bfloat16* __restrict__ Blo,
                 float* __restrict__ C, int N, int K)
{
    extern __shared__ __align__(128) char smem[];
    const uint32_t sb = smem_u32(smem);
    const int tid  = threadIdx.x;
    const int lane = tid & 31, wid = tid >> 5;
    const int wm = wid & 3;
    const int wn = wid >> 2;
    const int m0 = blockIdx.y * 128;
    const int n0 = blockIdx.x * 128;

    const __nv_bfloat16* srcs[4] = {
        Ahi + (size_t)m0 * K, Alo + (size_t)m0 * K,
        Bhi + (size_t)n0 * K, Blo + (size_t)n0 * K };

    const int NC = K / BK;

    auto preload = [&](int chunk, int s) {
        const uint32_t stg = sb + s * STAGE_B;
        const int k0 = chunk * BK;
#pragma unroll
        for (int it = 0; it < 8; it++) {
            int idx = tid + it * 256;
            int t = idx >> 9, rem = idx & 511;
            int r = rem >> 2, c = rem & 3;
            cp16(stg + t * TILE_B + r * 80 + c * 16,
                 srcs[t] + (size_t)r * K + k0 + c * 8);
        }
        CP_COMMIT();
    };

    float acc[2][8][4];
#pragma unroll
    for (int i = 0; i < 2; i++)
#pragma unroll
        for (int j = 0; j < 8; j++)
#pragma unroll
            for (int q = 0; q < 4; q++) acc[i][j][q] = 0.f;

    const int lrow  = lane & 15;
    const int lcol8 = (lane >> 4) * 8;

    preload(0, 0);

    for (int i = 0; i < NC; i++) {
        const int s = i & 1;
        if (i + 1 < NC) { preload(i + 1, s ^ 1); CP_WAIT(1); }
        else           { CP_WAIT(0); }
        __syncthreads();

        const uint32_t stg = sb + s * STAGE_B;
        const int pa[3] = {0, 0, 1}, pb[3] = {0, 1, 0};
#pragma unroll
        for (int p = 0; p < 3; p++) {
            const uint32_t aT = stg + pa[p] * TILE_B;
            const uint32_t bT = stg + (2 + pb[p]) * TILE_B;
#pragma unroll
            for (int ks = 0; ks < 2; ks++) {
                const int kc = ks * 16 + lcol8;
                uint32_t a[2][4];
#pragma unroll
                for (int mf = 0; mf < 2; mf++) {
                    uint32_t addr = aT + (uint32_t)((wm * 32 + mf * 16 + lrow) * 80 + kc * 2);
                    LDSM_X4(a[mf][0], a[mf][1], a[mf][2], a[mf][3], addr);
                }
                uint32_t b[4][4];
#pragma unroll
                for (int nt = 0; nt < 4; nt++) {
                    uint32_t addr = bT + (uint32_t)((wn * 64 + nt * 16 + lrow) * 80 + kc * 2);
                    LDSM_X4(b[nt][0], b[nt][1], b[nt][2], b[nt][3], addr);
                }
#pragma unroll
                for (int mf = 0; mf < 2; mf++)
#pragma unroll
                    for (int nt = 0; nt < 4; nt++) {
                        MMA_BF16(acc[mf][2 * nt + 0], a[mf], b[nt][0], b[nt][2]);
                        MMA_BF16(acc[mf][2 * nt + 1], a[mf], b[nt][1], b[nt][3]);
                    }
            }
        }
        __syncthreads();
    }

#pragma unroll
    for (int mf = 0; mf < 2; mf++) {
        const int row = m0 + wm * 32 + mf * 16 + (lane >> 2);
#pragma unroll
        for (int nf = 0; nf < 8; nf++) {
            const int col = n0 + wn * 64 + nf * 8 + 2 * (lane & 3);
            float* c0 = C + (size_t)row * N + col;
            float* c1 = C + (size_t)(row + 8) * N + col;
            c0[0] = acc[mf][nf][0]; c0[1] = acc[mf][nf][1];
            c1[0] = acc[mf][nf][2]; c1[1] = acc[mf][nf][3];
        }
    }
}

// ---------------------------------------------------------------------------
// Flash attention (fp32, causal) — R10 structure with float4-vectorized
// inner-loop smem access (LDS.128) in both the S and P·V loops.
// ---------------------------------------------------------------------------
#define PAD 68
#define ATT_SMEM_FLOATS (4 * 64 * PAD)
#define ATT_SMEM_BYTES  (ATT_SMEM_FLOATS * 4)

__global__ __launch_bounds__(256, 2)
void attn_kernel(const float* __restrict__ qkv, float* __restrict__ ycat)
{
    extern __shared__ float sm[];
    float* Qt = sm;                  // [64][PAD]  Qt[d*PAD + r]
    float* Kt = Qt + 64 * PAD;       // [64][PAD]  Kt[d*PAD + c]
    float* Vs = Kt + 64 * PAD;       // [64][PAD]  Vs[j*PAD + d]
    float* Ss = Vs + 64 * PAD;       // [64][PAD]  Ss[r*PAD + c]  (holds P)

    const int qi  = blockIdx.x;
    const int bhg = blockIdx.y;
    const int g = bhg & 3;
    const int h = (bhg >> 2) & 15;
    const int b = bhg >> 6;

    const float* qbase = qkv + (size_t)(b * SEQ) * QKV_N + g * CEMB + h * HDIM;
    const float* kbase = qkv + (size_t)(b * SEQ) * QKV_N + NQS * CEMB + h * HDIM;
    const float* vbase = qkv + (size_t)(b * SEQ) * QKV_N + (NQS + 1) * CEMB + h * HDIM;

    const int tid = threadIdx.x;
    const int tx = tid & 15, ty = tid >> 4;

    // load Q tile (transposed into Qt[d][r])
    for (int idx = tid; idx < 64 * 64; idx += 256) {
        int r = idx >> 6, d = idx & 63;
        Qt[d * PAD + r] = qbase[(size_t)(qi * 64 + r) * QKV_N + d];
    }

    float o[4][4];
#pragma unroll
    for (int i = 0; i < 4; i++)
#pragma unroll
        for (int j = 0; j < 4; j++) o[i][j] = 0.f;

    float m_r[4], l_r[4];            // per-row stats, replicated across tx
#pragma unroll
    for (int i = 0; i < 4; i++) { m_r[i] = -INFINITY; l_r[i] = 0.f; }

    const int rowg0 = qi * 64 + ty * 4;   // this thread's first global q-row

    for (int kj = 0; kj <= qi; kj++) {
        __syncthreads();   // prior iteration's Kt/Vs/Ss reads complete
        for (int idx = tid; idx < 64 * 64; idx += 256) {
            int r = idx >> 6, d = idx & 63;
            float kv = kbase[(size_t)(kj * 64 + r) * QKV_N + d];
            float vv = vbase[(size_t)(kj * 64 + r) * QKV_N + d];
            Kt[d * PAD + r] = kv;
            Vs[r * PAD + d] = vv;
        }
        __syncthreads();

        // S = (Q K^T): per d, 2x LDS.128 + 16 FMA
        float s[4][4];
#pragma unroll
        for (int i = 0; i < 4; i++)
#pragma unroll
            for (int j = 0; j < 4; j++) s[i][j] = 0.f;

        const float* qcol = &Qt[ty * 4];
        const float* kcol = &Kt[tx * 4];
        for (int d = 0; d < 64; d++) {
            float4 q4 = *(const float4*)(qcol + d * PAD);
            float4 k4 = *(const float4*)(kcol + d * PAD);
            float qv[4] = {q4.x, q4.y, q4.z, q4.w};
            float kv[4] = {k4.x, k4.y, k4.z, k4.w};
#pragma unroll
            for (int i = 0; i < 4; i++)
#pragma unroll
                for (int j = 0; j < 4; j++)
                    s[i][j] = fmaf(qv[i], kv[j], s[i][j]);
        }

        // scale + causal mask (global col > global row -> -inf)
        const int colg0 = kj * 64 + tx * 4;
#pragma unroll
        for (int i = 0; i < 4; i++) {
            const int rowg = rowg0 + i;
#pragma unroll
            for (int j = 0; j < 4; j++)
                s[i][j] = (colg0 + j > rowg) ? -INFINITY : s[i][j] * 0.125f;
        }

        // parallel online softmax: reduce across the 16 tx-threads of each row
#pragma unroll
        for (int i = 0; i < 4; i++) {
            float mx = fmaxf(fmaxf(s[i][0], s[i][1]), fmaxf(s[i][2], s[i][3]));
#pragma unroll
            for (int dd = 8; dd >= 1; dd >>= 1)
                mx = fmaxf(mx, __shfl_xor_sync(0xffffffffu, mx, dd));

            float nm = fmaxf(m_r[i], mx);
            float al = __expf(m_r[i] - nm);
            m_r[i] = nm;

            float p0 = __expf(s[i][0] - nm);
            float p1 = __expf(s[i][1] - nm);
            float p2 = __expf(s[i][2] - nm);
            float p3 = __expf(s[i][3] - nm);
            float sum = (p0 + p1) + (p2 + p3);
#pragma unroll
            for (int dd = 8; dd >= 1; dd >>= 1)
                sum += __shfl_xor_sync(0xffffffffu, sum, dd);
            l_r[i] = l_r[i] * al + sum;

            // rescale O and stash P (row-major, contiguous float4)
#pragma unroll
            for (int j = 0; j < 4; j++) o[i][j] *= al;
            *(float4*)&Ss[(ty * 4 + i) * PAD + tx * 4] =
                make_float4(p0, p1, p2, p3);
        }
        __syncthreads();   // P visible to all

        // O += P @ V: blocked by 4 keys; 8x LDS.128 + 64 FMA per block
        const float* vcol = &Vs[tx * 4];
        for (int j4 = 0; j4 < 16; j4++) {
            float4 pf[4], vf[4];
#pragma unroll
            for (int i = 0; i < 4; i++)
                pf[i] = *(const float4*)&Ss[(ty * 4 + i) * PAD + j4 * 4];
#pragma unroll
            for (int u = 0; u < 4; u++)
                vf[u] = *(const float4*)(vcol + (j4 * 4 + u) * PAD);
#pragma unroll
            for (int i = 0; i < 4; i++) {
                float pr[4] = {pf[i].x, pf[i].y, pf[i].z, pf[i].w};
#pragma unroll
                for (int u = 0; u < 4; u++) {
                    float vv[4] = {vf[u].x, vf[u].y, vf[u].z, vf[u].w};
#pragma unroll
                    for (int j = 0; j < 4; j++)
                        o[i][j] = fmaf(pr[u], vv[j], o[i][j]);
                }
            }
        }
    }

    float* ybase = ycat + (size_t)(b * SEQ) * CAT_N + g * CEMB + h * HDIM;
#pragma unroll
    for (int i = 0; i < 4; i++) {
        int r = ty * 4 + i;
        float inv = 1.f / l_r[i];
        *(float4*)&ybase[(size_t)(qi * 64 + r) * CAT_N + tx * 4] =
            make_float4(o[i][0] * inv, o[i][1] * inv, o[i][2] * inv, o[i][3] * inv);
    }
}

// ---------------------------------------------------------------------------
extern "C" void kernel_launch(void* const* d_in, const int* in_sizes, int n_in,
                              void* d_out, int out_size)
{
    const float* x      = (const float*)d_in[0];   // [8,1024,1024]
    const float* W_attn = (const float*)d_in[1];   // [6144,1024]
    const float* W_proj = (const float*)d_in[2];   // [1024,4096]
    float* out = (float*)d_out;                    // [8,1024,1024]

    float *qkv, *ycat;
    __nv_bfloat16 *xhi, *xlo, *wahi, *walo, *ychi, *yclo, *wphi, *wplo;
    cudaGetSymbolAddress((void**)&qkv,  g_qkv);
    cudaGetSymbolAddress((void**)&ycat, g_ycat);
    cudaGetSymbolAddress((void**)&xhi,  g_xhi);
    cudaGetSymbolAddress((void**)&xlo,  g_xlo);
    cudaGetSymbolAddress((void**)&wahi, g_wahi);
    cudaGetSymbolAddress((void**)&walo, g_walo);
    cudaGetSymbolAddress((void**)&ychi, g_ychi);
    cudaGetSymbolAddress((void**)&yclo, g_yclo);
    cudaGetSymbolAddress((void**)&wphi, g_wphi);
    cudaGetSymbolAddress((void**)&wplo, g_wplo);

    cudaFuncSetAttribute(gemm_bf16x3,
                         cudaFuncAttributeMaxDynamicSharedMemorySize, GEMM_SMEM);
    cudaFuncSetAttribute(attn_kernel,
                         cudaFuncAttributeMaxDynamicSharedMemorySize, ATT_SMEM_BYTES);

    // 0) hi/lo conversions for GEMM1 operands
    {
        size_t n4 = (size_t)MROWS * CEMB / 4;
        cvt_hilo<<<(unsigned)((n4 + 255) / 256), 256>>>(x, xhi, xlo, n4);
        n4 = (size_t)QKV_N * CEMB / 4;
        cvt_hilo<<<(unsigned)((n4 + 255) / 256), 256>>>(W_attn, wahi, walo, n4);
    }

    // 1) qkv = x @ W_attn^T  (mma.sync bf16, 3-pass)
    {
        dim3 grid(QKV_N / 128, MROWS / 128);
        gemm_bf16x3<<<grid, 256, GEMM_SMEM>>>(xhi, xlo, wahi, walo, qkv, QKV_N, CEMB);
    }

    // 2) flash attention per (b,h,g) — parallel softmax + LDS.128 inner loops
    {
        dim3 grid(SEQ / 64, BATCH * NHEAD * NQS);
        attn_kernel<<<grid, 256, ATT_SMEM_BYTES>>>(qkv, ycat);
    }

    // 3) hi/lo conversions for GEMM2 operands
    {
        size_t n4 = (size_t)MROWS * CAT_N / 4;
        cvt_hilo<<<(unsigned)((n4 + 255) / 256), 256>>>(ycat, ychi, yclo, n4);
        n4 = (size_t)CEMB * CAT_N / 4;
        cvt_hilo<<<(unsigned)((n4 + 255) / 256), 256>>>(W_proj, wphi, wplo, n4);
    }

    // 4) out = ycat @ W_proj^T  (mma.sync bf16, 3-pass)
    {
        dim3 grid(CEMB / 128, MROWS / 128);
        gemm_bf16x3<<<grid, 256, GEMM_SMEM>>>(ychi, yclo, wphi, wplo, out, CEMB, CAT_N);
    }
}

// round 12
// speedup vs baseline: 1.1076x; 1.1076x over previous
#include <cuda_runtime.h>
#include <cuda_bf16.h>
#include <cstdint>
#include <cstddef>

// Problem constants
#define BATCH   8
#define SEQ     1024
#define CEMB    1024
#define NHEAD   16
#define HDIM    64
#define NQS     4
#define MROWS   (BATCH * SEQ)          // 8192
#define QKV_N   ((NQS + 2) * CEMB)     // 6144
#define CAT_N   (NQS * CEMB)           // 4096

// Scratch (allocation-free rule: __device__ globals)
__device__ float g_qkv [(size_t)MROWS * QKV_N];   // [8192,6144] fp32
__device__ float g_ycat[(size_t)MROWS * CAT_N];   // [8192,4096] fp32
__device__ __nv_bfloat16 g_xhi [(size_t)MROWS * CEMB];
__device__ __nv_bfloat16 g_xlo [(size_t)MROWS * CEMB];
__device__ __nv_bfloat16 g_wahi[(size_t)QKV_N * CEMB];
__device__ __nv_bfloat16 g_walo[(size_t)QKV_N * CEMB];
__device__ __nv_bfloat16 g_ychi[(size_t)MROWS * CAT_N];
__device__ __nv_bfloat16 g_yclo[(size_t)MROWS * CAT_N];
__device__ __nv_bfloat16 g_wphi[(size_t)CEMB * CAT_N];
__device__ __nv_bfloat16 g_wplo[(size_t)CEMB * CAT_N];

// ---------------------------------------------------------------------------
// helpers
// ---------------------------------------------------------------------------
__device__ __forceinline__ uint32_t smem_u32(const void* p) {
    uint32_t a;
    asm("{ .reg .u64 t; cvta.to.shared.u64 t, %1; cvt.u32.u64 %0, t; }"
        : "=r"(a) : "l"(p));
    return a;
}
__device__ __forceinline__ void cp16(uint32_t dst, const void* src) {
    asm volatile("cp.async.cg.shared.global [%0], [%1], 16;" :: "r"(dst), "l"(src) : "memory");
}
#define CP_COMMIT() asm volatile("cp.async.commit_group;" ::: "memory")
#define CP_WAIT(n)  asm volatile("cp.async.wait_group %0;" :: "n"(n) : "memory")

#define LDSM_X4(r0, r1, r2, r3, addr)                                          \
    asm volatile("ldmatrix.sync.aligned.m8n8.x4.shared.b16 {%0,%1,%2,%3}, [%4];" \
                 : "=r"(r0), "=r"(r1), "=r"(r2), "=r"(r3) : "r"(addr))

#define MMA_BF16(d, a, b0, b1)                                                 \
    asm volatile("mma.sync.aligned.m16n8k16.row.col.f32.bf16.bf16.f32 "        \
                 "{%0,%1,%2,%3}, {%4,%5,%6,%7}, {%8,%9}, {%0,%1,%2,%3};"       \
                 : "+f"((d)[0]), "+f"((d)[1]), "+f"((d)[2]), "+f"((d)[3])      \
                 : "r"((a)[0]), "r"((a)[1]), "r"((a)[2]), "r"((a)[3]),         \
                   "r"(b0), "r"(b1))

__device__ __forceinline__ void store_hilo2(float a, float b,
                                            __nv_bfloat16* hi, __nv_bfloat16* lo) {
    __nv_bfloat162 hv, lv;
    hv.x = __float2bfloat16(a); hv.y = __float2bfloat16(b);
    lv.x = __float2bfloat16(a - __bfloat162float(hv.x));
    lv.y = __float2bfloat16(b - __bfloat162float(hv.y));
    *(__nv_bfloat162*)hi = hv;
    *(__nv_bfloat162*)lo = lv;
}

// ---------------------------------------------------------------------------
// fp32 -> bf16 hi/lo split
// ---------------------------------------------------------------------------
__global__ __launch_bounds__(256)
void cvt_hilo(const float* __restrict__ s, __nv_bfloat16* __restrict__ hi,
              __nv_bfloat16* __restrict__ lo, size_t n4)
{
    size_t i = (size_t)blockIdx.x * blockDim.x + threadIdx.x;
    if (i >= n4) return;
    float4 v = ((const float4*)s)[i];
    store_hilo2(v.x, v.y, hi + 4 * i, lo + 4 * i);
    store_hilo2(v.z, v.w, hi + 4 * i + 2, lo + 4 * i + 2);
}

// ---------------------------------------------------------------------------
// C[M,N] = A[M,K] @ B[N,K]^T via mma.sync bf16, 3-pass hi/lo split.
// CTA tile 128x128, BK=32, cp.async double buffer, 8 warps of 32x64.
// EXACT R3-proven kernel (fp32 C output).
// ---------------------------------------------------------------------------
#define BK        32
#define TPAD      40
#define TILE_B    (128 * TPAD * 2)
#define STAGE_B   (4 * TILE_B)
#define GEMM_SMEM (2 * STAGE_B)

__global__ __launch_bounds__(256, 1)
void gemm_bf16x3(const __nv_bfloat16* __restrict__ Ahi, const __nv_bfloat16* __restrict__ Alo,
                 const __nv_bfloat16* __restrict__ Bhi, const __nv_bfloat16* __restrict__ Blo,
                 float* __restrict__ C, int N, int K)
{
    extern __shared__ __align__(128) char smem[];
    const uint32_t sb = smem_u32(smem);
    const int tid  = threadIdx.x;
    const int lane = tid & 31, wid = tid >> 5;
    const int wm = wid & 3;
    const int wn = wid >> 2;
    const int m0 = blockIdx.y * 128;
    const int n0 = blockIdx.x * 128;

    const __nv_bfloat16* srcs[4] = {
        Ahi + (size_t)m0 * K, Alo + (size_t)m0 * K,
        Bhi + (size_t)n0 * K, Blo + (size_t)n0 * K };

    const int NC = K / BK;

    auto preload = [&](int chunk, int s) {
        const uint32_t stg = sb + s * STAGE_B;
        const int k0 = chunk * BK;
#pragma unroll
        for (int it = 0; it < 8; it++) {
            int idx = tid + it * 256;
            int t = idx >> 9, rem = idx & 511;
            int r = rem >> 2, c = rem & 3;
            cp16(stg + t * TILE_B + r * 80 + c * 16,
                 srcs[t] + (size_t)r * K + k0 + c * 8);
        }
        CP_COMMIT();
    };

    float acc[2][8][4];
#pragma unroll
    for (int i = 0; i < 2; i++)
#pragma unroll
        for (int j = 0; j < 8; j++)
#pragma unroll
            for (int q = 0; q < 4; q++) acc[i][j][q] = 0.f;

    const int lrow  = lane & 15;
    const int lcol8 = (lane >> 4) * 8;

    preload(0, 0);

    for (int i = 0; i < NC; i++) {
        const int s = i & 1;
        if (i + 1 < NC) { preload(i + 1, s ^ 1); CP_WAIT(1); }
        else           { CP_WAIT(0); }
        __syncthreads();

        const uint32_t stg = sb + s * STAGE_B;
        const int pa[3] = {0, 0, 1}, pb[3] = {0, 1, 0};
#pragma unroll
        for (int p = 0; p < 3; p++) {
            const uint32_t aT = stg + pa[p] * TILE_B;
            const uint32_t bT = stg + (2 + pb[p]) * TILE_B;
#pragma unroll
            for (int ks = 0; ks < 2; ks++) {
                const int kc = ks * 16 + lcol8;
                uint32_t a[2][4];
#pragma unroll
                for (int mf = 0; mf < 2; mf++) {
                    uint32_t addr = aT + (uint32_t)((wm * 32 + mf * 16 + lrow) * 80 + kc * 2);
                    LDSM_X4(a[mf][0], a[mf][1], a[mf][2], a[mf][3], addr);
                }
                uint32_t b[4][4];
#pragma unroll
                for (int nt = 0; nt < 4; nt++) {
                    uint32_t addr = bT + (uint32_t)((wn * 64 + nt * 16 + lrow) * 80 + kc * 2);
                    LDSM_X4(b[nt][0], b[nt][1], b[nt][2], b[nt][3], addr);
                }
#pragma unroll
                for (int mf = 0; mf < 2; mf++)
#pragma unroll
                    for (int nt = 0; nt < 4; nt++) {
                        MMA_BF16(acc[mf][2 * nt + 0], a[mf], b[nt][0], b[nt][2]);
                        MMA_BF16(acc[mf][2 * nt + 1], a[mf], b[nt][1], b[nt][3]);
                    }
            }
        }
        __syncthreads();
    }

#pragma unroll
    for (int mf = 0; mf < 2; mf++) {
        const int row = m0 + wm * 32 + mf * 16 + (lane >> 2);
#pragma unroll
        for (int nf = 0; nf < 8; nf++) {
            const int col = n0 + wn * 64 + nf * 8 + 2 * (lane & 3);
            float* c0 = C + (size_t)row * N + col;
            float* c1 = C + (size_t)(row + 8) * N + col;
            c0[0] = acc[mf][nf][0]; c0[1] = acc[mf][nf][1];
            c1[0] = acc[mf][nf][2]; c1[1] = acc[mf][nf][3];
        }
    }
}

// ---------------------------------------------------------------------------
// Flash attention (fp32, causal). 128 Q rows/block, 64-key tiles, 8x4 thread
// tile (256 threads = 16 row-groups x 16 col-groups). Parallel softmax via
// shfl over the 16 tx-threads sharing each row. Higher arithmetic intensity:
// S loop 12 words / 32 FMA; P.V loop 48 words / 128 FMA per 4-key block.
// ---------------------------------------------------------------------------
#define QPAD 132
#define KPAD 68
#define ATT_SMEM_FLOATS (64 * QPAD + 2 * 64 * KPAD + 128 * KPAD)
#define ATT_SMEM_BYTES  (ATT_SMEM_FLOATS * 4)   // 103424

__global__ __launch_bounds__(256, 2)
void attn_kernel(const float* __restrict__ qkv, float* __restrict__ ycat)
{
    extern __shared__ float sm[];
    float* Qt = sm;                       // [64][QPAD]  Qt[d*QPAD + r], r<128
    float* Kt = Qt + 64 * QPAD;           // [64][KPAD]  Kt[d*KPAD + c], c<64
    float* Vs = Kt + 64 * KPAD;           // [64][KPAD]  Vs[j*KPAD + d]
    float* Ss = Vs + 64 * KPAD;           // [128][KPAD] Ss[r*KPAD + c]  (P)

    const int qi  = blockIdx.x;           // 0..7 (128-row q tiles)
    const int bhg = blockIdx.y;
    const int g = bhg & 3;
    const int h = (bhg >> 2) & 15;
    const int b = bhg >> 6;
    const int q0 = qi * 128;

    const float* qbase = qkv + (size_t)(b * SEQ) * QKV_N + g * CEMB + h * HDIM;
    const float* kbase = qkv + (size_t)(b * SEQ) * QKV_N + NQS * CEMB + h * HDIM;
    const float* vbase = qkv + (size_t)(b * SEQ) * QKV_N + (NQS + 1) * CEMB + h * HDIM;

    const int tid = threadIdx.x;
    const int tx = tid & 15, ty = tid >> 4;

    // load Q tile (transposed into Qt[d][r]), 128 rows
    for (int idx = tid; idx < 128 * 64; idx += 256) {
        int r = idx >> 6, d = idx & 63;
        Qt[d * QPAD + r] = qbase[(size_t)(q0 + r) * QKV_N + d];
    }

    float o[8][4];
#pragma unroll
    for (int i = 0; i < 8; i++)
#pragma unroll
        for (int j = 0; j < 4; j++) o[i][j] = 0.f;

    float m_r[8], l_r[8];                 // per-row stats, replicated across tx
#pragma unroll
    for (int i = 0; i < 8; i++) { m_r[i] = -INFINITY; l_r[i] = 0.f; }

    const int rowg0 = q0 + ty * 8;        // this thread's first global q-row
    const int last = 2 * qi + 1;          // causal tile bound

    for (int kj = 0; kj <= last; kj++) {
        __syncthreads();   // prior iteration's Kt/Vs/Ss reads complete
        for (int idx = tid; idx < 64 * 64; idx += 256) {
            int r = idx >> 6, d = idx & 63;
            float kv = kbase[(size_t)(kj * 64 + r) * QKV_N + d];
            float vv = vbase[(size_t)(kj * 64 + r) * QKV_N + d];
            Kt[d * KPAD + r] = kv;
            Vs[r * KPAD + d] = vv;
        }
        __syncthreads();

        // S = Q K^T  (thread: rows ty*8.., cols tx*4..)
        float s[8][4];
#pragma unroll
        for (int i = 0; i < 8; i++)
#pragma unroll
            for (int j = 0; j < 4; j++) s[i][j] = 0.f;

        const float* qcol = &Qt[ty * 8];
        const float* kcol = &Kt[tx * 4];
        for (int d = 0; d < 64; d++) {
            float4 qa = *(const float4*)(qcol + d * QPAD);
            float4 qb = *(const float4*)(qcol + d * QPAD + 4);
            float4 k4 = *(const float4*)(kcol + d * KPAD);
            float qv[8] = {qa.x, qa.y, qa.z, qa.w, qb.x, qb.y, qb.z, qb.w};
            float kv[4] = {k4.x, k4.y, k4.z, k4.w};
#pragma unroll
            for (int i = 0; i < 8; i++)
#pragma unroll
                for (int j = 0; j < 4; j++)
                    s[i][j] = fmaf(qv[i], kv[j], s[i][j]);
        }

        // scale + causal mask (global col > global row -> -inf)
        const int colg0 = kj * 64 + tx * 4;
#pragma unroll
        for (int i = 0; i < 8; i++) {
            const int rowg = rowg0 + i;
#pragma unroll
            for (int j = 0; j < 4; j++)
                s[i][j] = (colg0 + j > rowg) ? -INFINITY : s[i][j] * 0.125f;
        }

        // parallel online softmax: reduce across the 16 tx-threads of each row
#pragma unroll
        for (int i = 0; i < 8; i++) {
            float mx = fmaxf(fmaxf(s[i][0], s[i][1]), fmaxf(s[i][2], s[i][3]));
#pragma unroll
            for (int dd = 8; dd >= 1; dd >>= 1)
                mx = fmaxf(mx, __shfl_xor_sync(0xffffffffu, mx, dd));

            float nm = fmaxf(m_r[i], mx);
            float al = __expf(m_r[i] - nm);
            m_r[i] = nm;

            float p0 = __expf(s[i][0] - nm);
            float p1 = __expf(s[i][1] - nm);
            float p2 = __expf(s[i][2] - nm);
            float p3 = __expf(s[i][3] - nm);
            float sum = (p0 + p1) + (p2 + p3);
#pragma unroll
            for (int dd = 8; dd >= 1; dd >>= 1)
                sum += __shfl_xor_sync(0xffffffffu, sum, dd);
            l_r[i] = l_r[i] * al + sum;

#pragma unroll
            for (int j = 0; j < 4; j++) o[i][j] *= al;
            *(float4*)&Ss[(ty * 8 + i) * KPAD + tx * 4] =
                make_float4(p0, p1, p2, p3);
        }
        __syncthreads();   // P visible to all

        // O += P @ V, blocked by 4 keys: 12 LDS.128 per 128 FMA
        const float* vcol = &Vs[tx * 4];
        for (int j4 = 0; j4 < 16; j4++) {
            float4 vf[4];
#pragma unroll
            for (int u = 0; u < 4; u++)
                vf[u] = *(const float4*)(vcol + (j4 * 4 + u) * KPAD);
            float vv[4][4] = {
                {vf[0].x, vf[0].y, vf[0].z, vf[0].w},
                {vf[1].x, vf[1].y, vf[1].z, vf[1].w},
                {vf[2].x, vf[2].y, vf[2].z, vf[2].w},
                {vf[3].x, vf[3].y, vf[3].z, vf[3].w}};
#pragma unroll
            for (int i = 0; i < 8; i++) {
                float4 pf = *(const float4*)&Ss[(ty * 8 + i) * KPAD + j4 * 4];
                float pr[4] = {pf.x, pf.y, pf.z, pf.w};
#pragma unroll
                for (int u = 0; u < 4; u++)
#pragma unroll
                    for (int j = 0; j < 4; j++)
                        o[i][j] = fmaf(pr[u], vv[u][j], o[i][j]);
            }
        }
    }

    float* ybase = ycat + (size_t)(b * SEQ) * CAT_N + g * CEMB + h * HDIM;
#pragma unroll
    for (int i = 0; i < 8; i++) {
        int r = ty * 8 + i;
        float inv = 1.f / l_r[i];
        *(float4*)&ybase[(size_t)(q0 + r) * CAT_N + tx * 4] =
            make_float4(o[i][0] * inv, o[i][1] * inv, o[i][2] * inv, o[i][3] * inv);
    }
}

// ---------------------------------------------------------------------------
extern "C" void kernel_launch(void* const* d_in, const int* in_sizes, int n_in,
                              void* d_out, int out_size)
{
    const float* x      = (const float*)d_in[0];   // [8,1024,1024]
    const float* W_attn = (const float*)d_in[1];   // [6144,1024]
    const float* W_proj = (const float*)d_in[2];   // [1024,4096]
    float* out = (float*)d_out;                    // [8,1024,1024]

    float *qkv, *ycat;
    __nv_bfloat16 *xhi, *xlo, *wahi, *walo, *ychi, *yclo, *wphi, *wplo;
    cudaGetSymbolAddress((void**)&qkv,  g_qkv);
    cudaGetSymbolAddress((void**)&ycat, g_ycat);
    cudaGetSymbolAddress((void**)&xhi,  g_xhi);
    cudaGetSymbolAddress((void**)&xlo,  g_xlo);
    cudaGetSymbolAddress((void**)&wahi, g_wahi);
    cudaGetSymbolAddress((void**)&walo, g_walo);
    cudaGetSymbolAddress((void**)&ychi, g_ychi);
    cudaGetSymbolAddress((void**)&yclo, g_yclo);
    cudaGetSymbolAddress((void**)&wphi, g_wphi);
    cudaGetSymbolAddress((void**)&wplo, g_wplo);

    cudaFuncSetAttribute(gemm_bf16x3,
                         cudaFuncAttributeMaxDynamicSharedMemorySize, GEMM_SMEM);
    cudaFuncSetAttribute(attn_kernel,
                         cudaFuncAttributeMaxDynamicSharedMemorySize, ATT_SMEM_BYTES);

    // 0) hi/lo conversions for GEMM1 operands
    {
        size_t n4 = (size_t)MROWS * CEMB / 4;
        cvt_hilo<<<(unsigned)((n4 + 255) / 256), 256>>>(x, xhi, xlo, n4);
        n4 = (size_t)QKV_N * CEMB / 4;
        cvt_hilo<<<(unsigned)((n4 + 255) / 256), 256>>>(W_attn, wahi, walo, n4);
    }

    // 1) qkv = x @ W_attn^T  (mma.sync bf16, 3-pass)
    {
        dim3 grid(QKV_N / 128, MROWS / 128);
        gemm_bf16x3<<<grid, 256, GEMM_SMEM>>>(xhi, xlo, wahi, walo, qkv, QKV_N, CEMB);
    }

    // 2) flash attention per (b,h,g) — 128-row tiles, 8x4 thread tile
    {
        dim3 grid(SEQ / 128, BATCH * NHEAD * NQS);
        attn_kernel<<<grid, 256, ATT_SMEM_BYTES>>>(qkv, ycat);
    }

    // 3) hi/lo conversions for GEMM2 operands
    {
        size_t n4 = (size_t)MROWS * CAT_N / 4;
        cvt_hilo<<<(unsigned)((n4 + 255) / 256), 256>>>(ycat, ychi, yclo, n4);
        n4 = (size_t)CEMB * CAT_N / 4;
        cvt_hilo<<<(unsigned)((n4 + 255) / 256), 256>>>(W_proj, wphi, wplo, n4);
    }

    // 4) out = ycat @ W_proj^T  (mma.sync bf16, 3-pass)
    {
        dim3 grid(CEMB / 128, MROWS / 128);
        gemm_bf16x3<<<grid, 256, GEMM_SMEM>>>(ychi, yclo, wphi, wplo, out, CEMB, CAT_N);
    }
}

// round 13
// speedup vs baseline: 1.1800x; 1.0653x over previous
#include <cuda_runtime.h>
#include <cuda_bf16.h>
#include <cstdint>
#include <cstddef>

// Problem constants
#define BATCH   8
#define SEQ     1024
#define CEMB    1024
#define NHEAD   16
#define HDIM    64
#define NQS     4
#define MROWS   (BATCH * SEQ)          // 8192
#define QKV_N   ((NQS + 2) * CEMB)     // 6144
#define CAT_N   (NQS * CEMB)           // 4096

// Scratch (allocation-free rule: __device__ globals)
__device__ float g_qkv [(size_t)MROWS * QKV_N];   // [8192,6144] fp32
__device__ float g_ycat[(size_t)MROWS * CAT_N];   // [8192,4096] fp32
__device__ __nv_bfloat16 g_xhi [(size_t)MROWS * CEMB];
__device__ __nv_bfloat16 g_xlo [(size_t)MROWS * CEMB];
__device__ __nv_bfloat16 g_wahi[(size_t)QKV_N * CEMB];
__device__ __nv_bfloat16 g_walo[(size_t)QKV_N * CEMB];
__device__ __nv_bfloat16 g_ychi[(size_t)MROWS * CAT_N];
__device__ __nv_bfloat16 g_yclo[(size_t)MROWS * CAT_N];
__device__ __nv_bfloat16 g_wphi[(size_t)CEMB * CAT_N];
__device__ __nv_bfloat16 g_wplo[(size_t)CEMB * CAT_N];

// ---------------------------------------------------------------------------
// helpers
// ---------------------------------------------------------------------------
__device__ __forceinline__ uint32_t smem_u32(const void* p) {
    uint32_t a;
    asm("{ .reg .u64 t; cvta.to.shared.u64 t, %1; cvt.u32.u64 %0, t; }"
        : "=r"(a) : "l"(p));
    return a;
}
__device__ __forceinline__ void cp16(uint32_t dst, const void* src) {
    asm volatile("cp.async.cg.shared.global [%0], [%1], 16;" :: "r"(dst), "l"(src) : "memory");
}
#define CP_COMMIT() asm volatile("cp.async.commit_group;" ::: "memory")
#define CP_WAIT(n)  asm volatile("cp.async.wait_group %0;" :: "n"(n) : "memory")

#define LDSM_X4(r0, r1, r2, r3, addr)                                          \
    asm volatile("ldmatrix.sync.aligned.m8n8.x4.shared.b16 {%0,%1,%2,%3}, [%4];" \
                 : "=r"(r0), "=r"(r1), "=r"(r2), "=r"(r3) : "r"(addr))

#define MMA_BF16(d, a, b0, b1)                                                 \
    asm volatile("mma.sync.aligned.m16n8k16.row.col.f32.bf16.bf16.f32 "        \
                 "{%0,%1,%2,%3}, {%4,%5,%6,%7}, {%8,%9}, {%0,%1,%2,%3};"       \
                 : "+f"((d)[0]), "+f"((d)[1]), "+f"((d)[2]), "+f"((d)[3])      \
                 : "r"((a)[0]), "r"((a)[1]), "r"((a)[2]), "r"((a)[3]),         \
                   "r"(b0), "r"(b1))

__device__ __forceinline__ void store_hilo2(float a, float b,
                                            __nv_bfloat16* hi, __nv_bfloat16* lo) {
    __nv_bfloat162 hv, lv;
    hv.x = __float2bfloat16(a); hv.y = __float2bfloat16(b);
    lv.x = __float2bfloat16(a - __bfloat162float(hv.x));
    lv.y = __float2bfloat16(b - __bfloat162float(hv.y));
    *(__nv_bfloat162*)hi = hv;
    *(__nv_bfloat162*)lo = lv;
}

// ---------------------------------------------------------------------------
// fp32 -> bf16 hi/lo split
// ---------------------------------------------------------------------------
__global__ __launch_bounds__(256)
void cvt_hilo(const float* __restrict__ s, __nv_bfloat16* __restrict__ hi,
              __nv_bfloat16* __restrict__ lo, size_t n4)
{
    size_t i = (size_t)blockIdx.x * blockDim.x + threadIdx.x;
    if (i >= n4) return;
    float4 v = ((const float4*)s)[i];
    store_hilo2(v.x, v.y, hi + 4 * i, lo + 4 * i);
    store_hilo2(v.z, v.w, hi + 4 * i + 2, lo + 4 * i + 2);
}

// ---------------------------------------------------------------------------
// C[M,N] = A[M,K] @ B[N,K]^T via mma.sync bf16, 3-pass hi/lo split.
// CTA tile 128x128, BK=32, cp.async double buffer, 8 warps of 32x64.
// R13: launch_bounds(256,2) for 2 CTAs/SM; fragment reuse across passes
// (Ahi*Bhi, Alo*Bhi, Ahi*Blo) -> 12 LDSM_X4 per ks instead of 18.
// ---------------------------------------------------------------------------
#define BK        32
#define TPAD      40
#define TILE_B    (128 * TPAD * 2)
#define STAGE_B   (4 * TILE_B)
#define GEMM_SMEM (2 * STAGE_B)

__global__ __launch_bounds__(256, 2)
void gemm_bf16x3(const __nv_bfloat16* __restrict__ Ahi, const __nv_bfloat16* __restrict__ Alo,
                 const __nv_bfloat16* __restrict__ Bhi, const __nv_bfloat16* __restrict__ Blo,
                 float* __restrict__ C, int N, int K)
{
    extern __shared__ __align__(128) char smem[];
    const uint32_t sb = smem_u32(smem);
    const int tid  = threadIdx.x;
    const int lane = tid & 31, wid = tid >> 5;
    const int wm = wid & 3;
    const int wn = wid >> 2;
    const int m0 = blockIdx.y * 128;
    const int n0 = blockIdx.x * 128;

    const __nv_bfloat16* srcs[4] = {
        Ahi + (size_t)m0 * K, Alo + (size_t)m0 * K,
        Bhi + (size_t)n0 * K, Blo + (size_t)n0 * K };

    const int NC = K / BK;

    auto preload = [&](int chunk, int s) {
        const uint32_t stg = sb + s * STAGE_B;
        const int k0 = chunk * BK;
#pragma unroll
        for (int it = 0; it < 8; it++) {
            int idx = tid + it * 256;
            int t = idx >> 9, rem = idx & 511;
            int r = rem >> 2, c = rem & 3;
            cp16(stg + t * TILE_B + r * 80 + c * 16,
                 srcs[t] + (size_t)r * K + k0 + c * 8);
        }
        CP_COMMIT();
    };

    float acc[2][8][4];
#pragma unroll
    for (int i = 0; i < 2; i++)
#pragma unroll
        for (int j = 0; j < 8; j++)
#pragma unroll
            for (int q = 0; q < 4; q++) acc[i][j][q] = 0.f;

    const int lrow  = lane & 15;
    const int lcol8 = (lane >> 4) * 8;

    preload(0, 0);

    for (int i = 0; i < NC; i++) {
        const int s = i & 1;
        if (i + 1 < NC) { preload(i + 1, s ^ 1); CP_WAIT(1); }
        else           { CP_WAIT(0); }
        __syncthreads();

        const uint32_t stg = sb + s * STAGE_B;
#pragma unroll
        for (int ks = 0; ks < 2; ks++) {
            const int kc = ks * 16 + lcol8;
            const uint32_t arow = (uint32_t)((wm * 32 + lrow) * 80 + kc * 2);
            const uint32_t brow = (uint32_t)((wn * 64 + lrow) * 80 + kc * 2);

            uint32_t ah[2][4], bh[4][4];
#pragma unroll
            for (int mf = 0; mf < 2; mf++)
                LDSM_X4(ah[mf][0], ah[mf][1], ah[mf][2], ah[mf][3],
                        stg + arow + (uint32_t)(mf * 16 * 80));
#pragma unroll
            for (int nt = 0; nt < 4; nt++)
                LDSM_X4(bh[nt][0], bh[nt][1], bh[nt][2], bh[nt][3],
                        stg + 2 * TILE_B + brow + (uint32_t)(nt * 16 * 80));
            // pass 1: Ahi * Bhi
#pragma unroll
            for (int mf = 0; mf < 2; mf++)
#pragma unroll
                for (int nt = 0; nt < 4; nt++) {
                    MMA_BF16(acc[mf][2 * nt + 0], ah[mf], bh[nt][0], bh[nt][2]);
                    MMA_BF16(acc[mf][2 * nt + 1], ah[mf], bh[nt][1], bh[nt][3]);
                }
            // pass 2: Alo * Bhi (reuse bh)
            {
                uint32_t al[2][4];
#pragma unroll
                for (int mf = 0; mf < 2; mf++)
                    LDSM_X4(al[mf][0], al[mf][1], al[mf][2], al[mf][3],
                            stg + TILE_B + arow + (uint32_t)(mf * 16 * 80));
#pragma unroll
                for (int mf = 0; mf < 2; mf++)
#pragma unroll
                    for (int nt = 0; nt < 4; nt++) {
                        MMA_BF16(acc[mf][2 * nt + 0], al[mf], bh[nt][0], bh[nt][2]);
                        MMA_BF16(acc[mf][2 * nt + 1], al[mf], bh[nt][1], bh[nt][3]);
                    }
            }
            // pass 3: Ahi * Blo (reuse ah)
            {
                uint32_t bl[4][4];
#pragma unroll
                for (int nt = 0; nt < 4; nt++)
                    LDSM_X4(bl[nt][0], bl[nt][1], bl[nt][2], bl[nt][3],
                            stg + 3 * TILE_B + brow + (uint32_t)(nt * 16 * 80));
#pragma unroll
                for (int mf = 0; mf < 2; mf++)
#pragma unroll
                    for (int nt = 0; nt < 4; nt++) {
                        MMA_BF16(acc[mf][2 * nt + 0], ah[mf], bl[nt][0], bl[nt][2]);
                        MMA_BF16(acc[mf][2 * nt + 1], ah[mf], bl[nt][1], bl[nt][3]);
                    }
            }
        }
        __syncthreads();
    }

#pragma unroll
    for (int mf = 0; mf < 2; mf++) {
        const int row = m0 + wm * 32 + mf * 16 + (lane >> 2);
#pragma unroll
        for (int nf = 0; nf < 8; nf++) {
            const int col = n0 + wn * 64 + nf * 8 + 2 * (lane & 3);
            float* c0 = C + (size_t)row * N + col;
            float* c1 = C + (size_t)(row + 8) * N + col;
            c0[0] = acc[mf][nf][0]; c0[1] = acc[mf][nf][1];
            c1[0] = acc[mf][nf][2]; c1[1] = acc[mf][nf][3];
        }
    }
}

// ---------------------------------------------------------------------------
// Flash attention (fp32, causal). 128 Q rows/block, 64-key tiles, 8x4 thread
// tile (256 threads = 16 row-groups x 16 col-groups). Parallel softmax via
// shfl over the 16 tx-threads sharing each row.  EXACT R12-proven kernel.
// ---------------------------------------------------------------------------
#define QPAD 132
#define KPAD 68
#define ATT_SMEM_FLOATS (64 * QPAD + 2 * 64 * KPAD + 128 * KPAD)
#define ATT_SMEM_BYTES  (ATT_SMEM_FLOATS * 4)   // 103424

__global__ __launch_bounds__(256, 2)
void attn_kernel(const float* __restrict__ qkv, float* __restrict__ ycat)
{
    extern __shared__ float sm[];
    float* Qt = sm;                       // [64][QPAD]  Qt[d*QPAD + r], r<128
    float* Kt = Qt + 64 * QPAD;           // [64][KPAD]  Kt[d*KPAD + c], c<64
    float* Vs = Kt + 64 * KPAD;           // [64][KPAD]  Vs[j*KPAD + d]
    float* Ss = Vs + 64 * KPAD;           // [128][KPAD] Ss[r*KPAD + c]  (P)

    const int qi  = blockIdx.x;           // 0..7 (128-row q tiles)
    const int bhg = blockIdx.y;
    const int g = bhg & 3;
    const int h = (bhg >> 2) & 15;
    const int b = bhg >> 6;
    const int q0 = qi * 128;

    const float* qbase = qkv + (size_t)(b * SEQ) * QKV_N + g * CEMB + h * HDIM;
    const float* kbase = qkv + (size_t)(b * SEQ) * QKV_N + NQS * CEMB + h * HDIM;
    const float* vbase = qkv + (size_t)(b * SEQ) * QKV_N + (NQS + 1) * CEMB + h * HDIM;

    const int tid = threadIdx.x;
    const int tx = tid & 15, ty = tid >> 4;

    // load Q tile (transposed into Qt[d][r]), 128 rows
    for (int idx = tid; idx < 128 * 64; idx += 256) {
        int r = idx >> 6, d = idx & 63;
        Qt[d * QPAD + r] = qbase[(size_t)(q0 + r) * QKV_N + d];
    }

    float o[8][4];
#pragma unroll
    for (int i = 0; i < 8; i++)
#pragma unroll
        for (int j = 0; j < 4; j++) o[i][j] = 0.f;

    float m_r[8], l_r[8];                 // per-row stats, replicated across tx
#pragma unroll
    for (int i = 0; i < 8; i++) { m_r[i] = -INFINITY; l_r[i] = 0.f; }

    const int rowg0 = q0 + ty * 8;        // this thread's first global q-row
    const int last = 2 * qi + 1;          // causal tile bound

    for (int kj = 0; kj <= last; kj++) {
        __syncthreads();   // prior iteration's Kt/Vs/Ss reads complete
        for (int idx = tid; idx < 64 * 64; idx += 256) {
            int r = idx >> 6, d = idx & 63;
            float kv = kbase[(size_t)(kj * 64 + r) * QKV_N + d];
            float vv = vbase[(size_t)(kj * 64 + r) * QKV_N + d];
            Kt[d * KPAD + r] = kv;
            Vs[r * KPAD + d] = vv;
        }
        __syncthreads();

        // S = Q K^T  (thread: rows ty*8.., cols tx*4..)
        float s[8][4];
#pragma unroll
        for (int i = 0; i < 8; i++)
#pragma unroll
            for (int j = 0; j < 4; j++) s[i][j] = 0.f;

        const float* qcol = &Qt[ty * 8];
        const float* kcol = &Kt[tx * 4];
        for (int d = 0; d < 64; d++) {
            float4 qa = *(const float4*)(qcol + d * QPAD);
            float4 qb = *(const float4*)(qcol + d * QPAD + 4);
            float4 k4 = *(const float4*)(kcol + d * KPAD);
            float qv[8] = {qa.x, qa.y, qa.z, qa.w, qb.x, qb.y, qb.z, qb.w};
            float kv[4] = {k4.x, k4.y, k4.z, k4.w};
#pragma unroll
            for (int i = 0; i < 8; i++)
#pragma unroll
                for (int j = 0; j < 4; j++)
                    s[i][j] = fmaf(qv[i], kv[j], s[i][j]);
        }

        // scale + causal mask (global col > global row -> -inf)
        const int colg0 = kj * 64 + tx * 4;
#pragma unroll
        for (int i = 0; i < 8; i++) {
            const int rowg = rowg0 + i;
#pragma unroll
            for (int j = 0; j < 4; j++)
                s[i][j] = (colg0 + j > rowg) ? -INFINITY : s[i][j] * 0.125f;
        }

        // parallel online softmax: reduce across the 16 tx-threads of each row
#pragma unroll
        for (int i = 0; i < 8; i++) {
            float mx = fmaxf(fmaxf(s[i][0], s[i][1]), fmaxf(s[i][2], s[i][3]));
#pragma unroll
            for (int dd = 8; dd >= 1; dd >>= 1)
                mx = fmaxf(mx, __shfl_xor_sync(0xffffffffu, mx, dd));

            float nm = fmaxf(m_r[i], mx);
            float al = __expf(m_r[i] - nm);
            m_r[i] = nm;

            float p0 = __expf(s[i][0] - nm);
            float p1 = __expf(s[i][1] - nm);
            float p2 = __expf(s[i][2] - nm);
            float p3 = __expf(s[i][3] - nm);
            float sum = (p0 + p1) + (p2 + p3);
#pragma unroll
            for (int dd = 8; dd >= 1; dd >>= 1)
                sum += __shfl_xor_sync(0xffffffffu, sum, dd);
            l_r[i] = l_r[i] * al + sum;

#pragma unroll
            for (int j = 0; j < 4; j++) o[i][j] *= al;
            *(float4*)&Ss[(ty * 8 + i) * KPAD + tx * 4] =
                make_float4(p0, p1, p2, p3);
        }
        __syncthreads();   // P visible to all

        // O += P @ V, blocked by 4 keys: 12 LDS.128 per 128 FMA
        const float* vcol = &Vs[tx * 4];
        for (int j4 = 0; j4 < 16; j4++) {
            float4 vf[4];
#pragma unroll
            for (int u = 0; u < 4; u++)
                vf[u] = *(const float4*)(vcol + (j4 * 4 + u) * KPAD);
            float vv[4][4] = {
                {vf[0].x, vf[0].y, vf[0].z, vf[0].w},
                {vf[1].x, vf[1].y, vf[1].z, vf[1].w},
                {vf[2].x, vf[2].y, vf[2].z, vf[2].w},
                {vf[3].x, vf[3].y, vf[3].z, vf[3].w}};
#pragma unroll
            for (int i = 0; i < 8; i++) {
                float4 pf = *(const float4*)&Ss[(ty * 8 + i) * KPAD + j4 * 4];
                float pr[4] = {pf.x, pf.y, pf.z, pf.w};
#pragma unroll
                for (int u = 0; u < 4; u++)
#pragma unroll
                    for (int j = 0; j < 4; j++)
                        o[i][j] = fmaf(pr[u], vv[u][j], o[i][j]);
            }
        }
    }

    float* ybase = ycat + (size_t)(b * SEQ) * CAT_N + g * CEMB + h * HDIM;
#pragma unroll
    for (int i = 0; i < 8; i++) {
        int r = ty * 8 + i;
        float inv = 1.f / l_r[i];
        *(float4*)&ybase[(size_t)(q0 + r) * CAT_N + tx * 4] =
            make_float4(o[i][0] * inv, o[i][1] * inv, o[i][2] * inv, o[i][3] * inv);
    }
}

// ---------------------------------------------------------------------------
extern "C" void kernel_launch(void* const* d_in, const int* in_sizes, int n_in,
                              void* d_out, int out_size)
{
    const float* x      = (const float*)d_in[0];   // [8,1024,1024]
    const float* W_attn = (const float*)d_in[1];   // [6144,1024]
    const float* W_proj = (const float*)d_in[2];   // [1024,4096]
    float* out = (float*)d_out;                    // [8,1024,1024]

    float *qkv, *ycat;
    __nv_bfloat16 *xhi, *xlo, *wahi, *walo, *ychi, *yclo, *wphi, *wplo;
    cudaGetSymbolAddress((void**)&qkv,  g_qkv);
    cudaGetSymbolAddress((void**)&ycat, g_ycat);
    cudaGetSymbolAddress((void**)&xhi,  g_xhi);
    cudaGetSymbolAddress((void**)&xlo,  g_xlo);
    cudaGetSymbolAddress((void**)&wahi, g_wahi);
    cudaGetSymbolAddress((void**)&walo, g_walo);
    cudaGetSymbolAddress((void**)&ychi, g_ychi);
    cudaGetSymbolAddress((void**)&yclo, g_yclo);
    cudaGetSymbolAddress((void**)&wphi, g_wphi);
    cudaGetSymbolAddress((void**)&wplo, g_wplo);

    cudaFuncSetAttribute(gemm_bf16x3,
                         cudaFuncAttributeMaxDynamicSharedMemorySize, GEMM_SMEM);
    cudaFuncSetAttribute(attn_kernel,
                         cudaFuncAttributeMaxDynamicSharedMemorySize, ATT_SMEM_BYTES);

    // 0) hi/lo conversions for GEMM1 operands
    {
        size_t n4 = (size_t)MROWS * CEMB / 4;
        cvt_hilo<<<(unsigned)((n4 + 255) / 256), 256>>>(x, xhi, xlo, n4);
        n4 = (size_t)QKV_N * CEMB / 4;
        cvt_hilo<<<(unsigned)((n4 + 255) / 256), 256>>>(W_attn, wahi, walo, n4);
    }

    // 1) qkv = x @ W_attn^T  (mma.sync bf16, 3-pass)
    {
        dim3 grid(QKV_N / 128, MROWS / 128);
        gemm_bf16x3<<<grid, 256, GEMM_SMEM>>>(xhi, xlo, wahi, walo, qkv, QKV_N, CEMB);
    }

    // 2) flash attention per (b,h,g) — 128-row tiles, 8x4 thread tile
    {
        dim3 grid(SEQ / 128, BATCH * NHEAD * NQS);
        attn_kernel<<<grid, 256, ATT_SMEM_BYTES>>>(qkv, ycat);
    }

    // 3) hi/lo conversions for GEMM2 operands
    {
        size_t n4 = (size_t)MROWS * CAT_N / 4;
        cvt_hilo<<<(unsigned)((n4 + 255) / 256), 256>>>(ycat, ychi, yclo, n4);
        n4 = (size_t)CEMB * CAT_N / 4;
        cvt_hilo<<<(unsigned)((n4 + 255) / 256), 256>>>(W_proj, wphi, wplo, n4);
    }

    // 4) out = ycat @ W_proj^T  (mma.sync bf16, 3-pass)
    {
        dim3 grid(CEMB / 128, MROWS / 128);
        gemm_bf16x3<<<grid, 256, GEMM_SMEM>>>(ychi, yclo, wphi, wplo, out, CEMB, CAT_N);
    }
}

// round 14
// speedup vs baseline: 1.2000x; 1.0170x over previous
#include <cuda_runtime.h>
#include <cuda_bf16.h>
#include <cstdint>
#include <cstddef>

// Problem constants
#define BATCH   8
#define SEQ     1024
#define CEMB    1024
#define NHEAD   16
#define HDIM    64
#define NQS     4
#define MROWS   (BATCH * SEQ)          // 8192
#define QKV_N   ((NQS + 2) * CEMB)     // 6144
#define CAT_N   (NQS * CEMB)           // 4096

// Scratch (allocation-free rule: __device__ globals)
__device__ float g_qkv [(size_t)MROWS * QKV_N];   // [8192,6144] fp32
__device__ __nv_bfloat16 g_xhi [(size_t)MROWS * CEMB];
__device__ __nv_bfloat16 g_xlo [(size_t)MROWS * CEMB];
__device__ __nv_bfloat16 g_wahi[(size_t)QKV_N * CEMB];
__device__ __nv_bfloat16 g_walo[(size_t)QKV_N * CEMB];
__device__ __nv_bfloat16 g_ychi[(size_t)MROWS * CAT_N];
__device__ __nv_bfloat16 g_yclo[(size_t)MROWS * CAT_N];
__device__ __nv_bfloat16 g_wphi[(size_t)CEMB * CAT_N];
__device__ __nv_bfloat16 g_wplo[(size_t)CEMB * CAT_N];

// ---------------------------------------------------------------------------
// helpers
// ---------------------------------------------------------------------------
__device__ __forceinline__ uint32_t smem_u32(const void* p) {
    uint32_t a;
    asm("{ .reg .u64 t; cvta.to.shared.u64 t, %1; cvt.u32.u64 %0, t; }"
        : "=r"(a) : "l"(p));
    return a;
}
__device__ __forceinline__ void cp16(uint32_t dst, const void* src) {
    asm volatile("cp.async.cg.shared.global [%0], [%1], 16;" :: "r"(dst), "l"(src) : "memory");
}
#define CP_COMMIT() asm volatile("cp.async.commit_group;" ::: "memory")
#define CP_WAIT(n)  asm volatile("cp.async.wait_group %0;" :: "n"(n) : "memory")

#define LDSM_X4(r0, r1, r2, r3, addr)                                          \
    asm volatile("ldmatrix.sync.aligned.m8n8.x4.shared.b16 {%0,%1,%2,%3}, [%4];" \
                 : "=r"(r0), "=r"(r1), "=r"(r2), "=r"(r3) : "r"(addr))

#define MMA_BF16(d, a, b0, b1)                                                 \
    asm volatile("mma.sync.aligned.m16n8k16.row.col.f32.bf16.bf16.f32 "        \
                 "{%0,%1,%2,%3}, {%4,%5,%6,%7}, {%8,%9}, {%0,%1,%2,%3};"       \
                 : "+f"((d)[0]), "+f"((d)[1]), "+f"((d)[2]), "+f"((d)[3])      \
                 : "r"((a)[0]), "r"((a)[1]), "r"((a)[2]), "r"((a)[3]),         \
                   "r"(b0), "r"(b1))

__device__ __forceinline__ void store_hilo2(float a, float b,
                                            __nv_bfloat16* hi, __nv_bfloat16* lo) {
    __nv_bfloat162 hv, lv;
    hv.x = __float2bfloat16(a); hv.y = __float2bfloat16(b);
    lv.x = __float2bfloat16(a - __bfloat162float(hv.x));
    lv.y = __float2bfloat16(b - __bfloat162float(hv.y));
    *(__nv_bfloat162*)hi = hv;
    *(__nv_bfloat162*)lo = lv;
}

// ---------------------------------------------------------------------------
// fp32 -> bf16 hi/lo split
// ---------------------------------------------------------------------------
__global__ __launch_bounds__(256)
void cvt_hilo(const float* __restrict__ s, __nv_bfloat16* __restrict__ hi,
              __nv_bfloat16* __restrict__ lo, size_t n4)
{
    size_t i = (size_t)blockIdx.x * blockDim.x + threadIdx.x;
    if (i >= n4) return;
    float4 v = ((const float4*)s)[i];
    store_hilo2(v.x, v.y, hi + 4 * i, lo + 4 * i);
    store_hilo2(v.z, v.w, hi + 4 * i + 2, lo + 4 * i + 2);
}

// ---------------------------------------------------------------------------
// C[M,N] = A[M,K] @ B[N,K]^T via mma.sync bf16, 3-pass hi/lo split.
// CTA tile 128x128, BK=32, cp.async double buffer, 8 warps of 32x64.
// EXACT R13-proven kernel: launch_bounds(256,2), fragment reuse across passes.
// ---------------------------------------------------------------------------
#define BK        32
#define TPAD      40
#define TILE_B    (128 * TPAD * 2)
#define STAGE_B   (4 * TILE_B)
#define GEMM_SMEM (2 * STAGE_B)

__global__ __launch_bounds__(256, 2)
void gemm_bf16x3(const __nv_bfloat16* __restrict__ Ahi, const __nv_bfloat16* __restrict__ Alo,
                 const __nv_bfloat16* __restrict__ Bhi, const __nv_bfloat16* __restrict__ Blo,
                 float* __restrict__ C, int N, int K)
{
    extern __shared__ __align__(128) char smem[];
    const uint32_t sb = smem_u32(smem);
    const int tid  = threadIdx.x;
    const int lane = tid & 31, wid = tid >> 5;
    const int wm = wid & 3;
    const int wn = wid >> 2;
    const int m0 = blockIdx.y * 128;
    const int n0 = blockIdx.x * 128;

    const __nv_bfloat16* srcs[4] = {
        Ahi + (size_t)m0 * K, Alo + (size_t)m0 * K,
        Bhi + (size_t)n0 * K, Blo + (size_t)n0 * K };

    const int NC = K / BK;

    auto preload = [&](int chunk, int s) {
        const uint32_t stg = sb + s * STAGE_B;
        const int k0 = chunk * BK;
#pragma unroll
        for (int it = 0; it < 8; it++) {
            int idx = tid + it * 256;
            int t = idx >> 9, rem = idx & 511;
            int r = rem >> 2, c = rem & 3;
            cp16(stg + t * TILE_B + r * 80 + c * 16,
                 srcs[t] + (size_t)r * K + k0 + c * 8);
        }
        CP_COMMIT();
    };

    float acc[2][8][4];
#pragma unroll
    for (int i = 0; i < 2; i++)
#pragma unroll
        for (int j = 0; j < 8; j++)
#pragma unroll
            for (int q = 0; q < 4; q++) acc[i][j][q] = 0.f;

    const int lrow  = lane & 15;
    const int lcol8 = (lane >> 4) * 8;

    preload(0, 0);

    for (int i = 0; i < NC; i++) {
        const int s = i & 1;
        if (i + 1 < NC) { preload(i + 1, s ^ 1); CP_WAIT(1); }
        else           { CP_WAIT(0); }
        __syncthreads();

        const uint32_t stg = sb + s * STAGE_B;
#pragma unroll
        for (int ks = 0; ks < 2; ks++) {
            const int kc = ks * 16 + lcol8;
            const uint32_t arow = (uint32_t)((wm * 32 + lrow) * 80 + kc * 2);
            const uint32_t brow = (uint32_t)((wn * 64 + lrow) * 80 + kc * 2);

            uint32_t ah[2][4], bh[4][4];
#pragma unroll
            for (int mf = 0; mf < 2; mf++)
                LDSM_X4(ah[mf][0], ah[mf][1], ah[mf][2], ah[mf][3],
                        stg + arow + (uint32_t)(mf * 16 * 80));
#pragma unroll
            for (int nt = 0; nt < 4; nt++)
                LDSM_X4(bh[nt][0], bh[nt][1], bh[nt][2], bh[nt][3],
                        stg + 2 * TILE_B + brow + (uint32_t)(nt * 16 * 80));
            // pass 1: Ahi * Bhi
#pragma unroll
            for (int mf = 0; mf < 2; mf++)
#pragma unroll
                for (int nt = 0; nt < 4; nt++) {
                    MMA_BF16(acc[mf][2 * nt + 0], ah[mf], bh[nt][0], bh[nt][2]);
                    MMA_BF16(acc[mf][2 * nt + 1], ah[mf], bh[nt][1], bh[nt][3]);
                }
            // pass 2: Alo * Bhi (reuse bh)
            {
                uint32_t al[2][4];
#pragma unroll
                for (int mf = 0; mf < 2; mf++)
                    LDSM_X4(al[mf][0], al[mf][1], al[mf][2], al[mf][3],
                            stg + TILE_B + arow + (uint32_t)(mf * 16 * 80));
#pragma unroll
                for (int mf = 0; mf < 2; mf++)
#pragma unroll
                    for (int nt = 0; nt < 4; nt++) {
                        MMA_BF16(acc[mf][2 * nt + 0], al[mf], bh[nt][0], bh[nt][2]);
                        MMA_BF16(acc[mf][2 * nt + 1], al[mf], bh[nt][1], bh[nt][3]);
                    }
            }
            // pass 3: Ahi * Blo (reuse ah)
            {
                uint32_t bl[4][4];
#pragma unroll
                for (int nt = 0; nt < 4; nt++)
                    LDSM_X4(bl[nt][0], bl[nt][1], bl[nt][2], bl[nt][3],
                            stg + 3 * TILE_B + brow + (uint32_t)(nt * 16 * 80));
#pragma unroll
                for (int mf = 0; mf < 2; mf++)
#pragma unroll
                    for (int nt = 0; nt < 4; nt++) {
                        MMA_BF16(acc[mf][2 * nt + 0], ah[mf], bl[nt][0], bl[nt][2]);
                        MMA_BF16(acc[mf][2 * nt + 1], ah[mf], bl[nt][1], bl[nt][3]);
                    }
            }
        }
        __syncthreads();
    }

#pragma unroll
    for (int mf = 0; mf < 2; mf++) {
        const int row = m0 + wm * 32 + mf * 16 + (lane >> 2);
#pragma unroll
        for (int nf = 0; nf < 8; nf++) {
            const int col = n0 + wn * 64 + nf * 8 + 2 * (lane & 3);
            float* c0 = C + (size_t)row * N + col;
            float* c1 = C + (size_t)(row + 8) * N + col;
            c0[0] = acc[mf][nf][0]; c0[1] = acc[mf][nf][1];
            c1[0] = acc[mf][nf][2]; c1[1] = acc[mf][nf][3];
        }
    }
}

// ---------------------------------------------------------------------------
// Flash attention (fp32, causal). 128 Q rows/block, 64-key tiles, 8x4 thread
// tile. R14: (a) interior tiles skip the causal-mask compare/select entirely;
// (b) epilogue writes ychi/yclo bf16 hi/lo directly (fused split).
// ---------------------------------------------------------------------------
#define QPAD 132
#define KPAD 68
#define ATT_SMEM_FLOATS (64 * QPAD + 2 * 64 * KPAD + 128 * KPAD)
#define ATT_SMEM_BYTES  (ATT_SMEM_FLOATS * 4)   // 103424

__global__ __launch_bounds__(256, 2)
void attn_kernel(const float* __restrict__ qkv,
                 __nv_bfloat16* __restrict__ ychi,
                 __nv_bfloat16* __restrict__ yclo)
{
    extern __shared__ float sm[];
    float* Qt = sm;                       // [64][QPAD]  Qt[d*QPAD + r], r<128
    float* Kt = Qt + 64 * QPAD;           // [64][KPAD]  Kt[d*KPAD + c], c<64
    float* Vs = Kt + 64 * KPAD;           // [64][KPAD]  Vs[j*KPAD + d]
    float* Ss = Vs + 64 * KPAD;           // [128][KPAD] Ss[r*KPAD + c]  (P)

    const int qi  = blockIdx.x;           // 0..7 (128-row q tiles)
    const int bhg = blockIdx.y;
    const int g = bhg & 3;
    const int h = (bhg >> 2) & 15;
    const int b = bhg >> 6;
    const int q0 = qi * 128;

    const float* qbase = qkv + (size_t)(b * SEQ) * QKV_N + g * CEMB + h * HDIM;
    const float* kbase = qkv + (size_t)(b * SEQ) * QKV_N + NQS * CEMB + h * HDIM;
    const float* vbase = qkv + (size_t)(b * SEQ) * QKV_N + (NQS + 1) * CEMB + h * HDIM;

    const int tid = threadIdx.x;
    const int tx = tid & 15, ty = tid >> 4;

    // load Q tile (transposed into Qt[d][r]), 128 rows
    for (int idx = tid; idx < 128 * 64; idx += 256) {
        int r = idx >> 6, d = idx & 63;
        Qt[d * QPAD + r] = qbase[(size_t)(q0 + r) * QKV_N + d];
    }

    float o[8][4];
#pragma unroll
    for (int i = 0; i < 8; i++)
#pragma unroll
        for (int j = 0; j < 4; j++) o[i][j] = 0.f;

    float m_r[8], l_r[8];                 // per-row stats, replicated across tx
#pragma unroll
    for (int i = 0; i < 8; i++) { m_r[i] = -INFINITY; l_r[i] = 0.f; }

    const int rowg0 = q0 + ty * 8;        // this thread's first global q-row
    const int last = 2 * qi + 1;          // causal tile bound

    for (int kj = 0; kj <= last; kj++) {
        __syncthreads();   // prior iteration's Kt/Vs/Ss reads complete
        for (int idx = tid; idx < 64 * 64; idx += 256) {
            int r = idx >> 6, d = idx & 63;
            float kv = kbase[(size_t)(kj * 64 + r) * QKV_N + d];
            float vv = vbase[(size_t)(kj * 64 + r) * QKV_N + d];
            Kt[d * KPAD + r] = kv;
            Vs[r * KPAD + d] = vv;
        }
        __syncthreads();

        // S = Q K^T  (thread: rows ty*8.., cols tx*4..)
        float s[8][4];
#pragma unroll
        for (int i = 0; i < 8; i++)
#pragma unroll
            for (int j = 0; j < 4; j++) s[i][j] = 0.f;

        const float* qcol = &Qt[ty * 8];
        const float* kcol = &Kt[tx * 4];
        for (int d = 0; d < 64; d++) {
            float4 qa = *(const float4*)(qcol + d * QPAD);
            float4 qb = *(const float4*)(qcol + d * QPAD + 4);
            float4 k4 = *(const float4*)(kcol + d * KPAD);
            float qv[8] = {qa.x, qa.y, qa.z, qa.w, qb.x, qb.y, qb.z, qb.w};
            float kv[4] = {k4.x, k4.y, k4.z, k4.w};
#pragma unroll
            for (int i = 0; i < 8; i++)
#pragma unroll
                for (int j = 0; j < 4; j++)
                    s[i][j] = fmaf(qv[i], kv[j], s[i][j]);
        }

        // scale + causal mask; interior tiles (fully below diagonal for this
        // thread's 8 rows) take the mask-free path
        if (kj * 64 + 63 <= rowg0) {
#pragma unroll
            for (int i = 0; i < 8; i++)
#pragma unroll
                for (int j = 0; j < 4; j++) s[i][j] *= 0.125f;
        } else {
            const int colg0 = kj * 64 + tx * 4;
#pragma unroll
            for (int i = 0; i < 8; i++) {
                const int rowg = rowg0 + i;
#pragma unroll
                for (int j = 0; j < 4; j++)
                    s[i][j] = (colg0 + j > rowg) ? -INFINITY : s[i][j] * 0.125f;
            }
        }

        // parallel online softmax: reduce across the 16 tx-threads of each row
#pragma unroll
        for (int i = 0; i < 8; i++) {
            float mx = fmaxf(fmaxf(s[i][0], s[i][1]), fmaxf(s[i][2], s[i][3]));
#pragma unroll
            for (int dd = 8; dd >= 1; dd >>= 1)
                mx = fmaxf(mx, __shfl_xor_sync(0xffffffffu, mx, dd));

            float nm = fmaxf(m_r[i], mx);
            float al = __expf(m_r[i] - nm);
            m_r[i] = nm;

            float p0 = __expf(s[i][0] - nm);
            float p1 = __expf(s[i][1] - nm);
            float p2 = __expf(s[i][2] - nm);
            float p3 = __expf(s[i][3] - nm);
            float sum = (p0 + p1) + (p2 + p3);
#pragma unroll
            for (int dd = 8; dd >= 1; dd >>= 1)
                sum += __shfl_xor_sync(0xffffffffu, sum, dd);
            l_r[i] = l_r[i] * al + sum;

#pragma unroll
            for (int j = 0; j < 4; j++) o[i][j] *= al;
            *(float4*)&Ss[(ty * 8 + i) * KPAD + tx * 4] =
                make_float4(p0, p1, p2, p3);
        }
        __syncthreads();   // P visible to all

        // O += P @ V, blocked by 4 keys: 12 LDS.128 per 128 FMA
        const float* vcol = &Vs[tx * 4];
        for (int j4 = 0; j4 < 16; j4++) {
            float4 vf[4];
#pragma unroll
            for (int u = 0; u < 4; u++)
                vf[u] = *(const float4*)(vcol + (j4 * 4 + u) * KPAD);
            float vv[4][4] = {
                {vf[0].x, vf[0].y, vf[0].z, vf[0].w},
                {vf[1].x, vf[1].y, vf[1].z, vf[1].w},
                {vf[2].x, vf[2].y, vf[2].z, vf[2].w},
                {vf[3].x, vf[3].y, vf[3].z, vf[3].w}};
#pragma unroll
            for (int i = 0; i < 8; i++) {
                float4 pf = *(const float4*)&Ss[(ty * 8 + i) * KPAD + j4 * 4];
                float pr[4] = {pf.x, pf.y, pf.z, pf.w};
#pragma unroll
                for (int u = 0; u < 4; u++)
#pragma unroll
                    for (int j = 0; j < 4; j++)
                        o[i][j] = fmaf(pr[u], vv[u][j], o[i][j]);
            }
        }
    }

    // epilogue: write bf16 hi/lo directly (fused split; same values as
    // the former fp32 ycat -> cvt_hilo chain)
    const size_t rowbase = (size_t)(b * SEQ) + q0;
    const int colbase = g * CEMB + h * HDIM + tx * 4;
#pragma unroll
    for (int i = 0; i < 8; i++) {
        size_t r = rowbase + ty * 8 + i;
        float inv = 1.f / l_r[i];
        __nv_bfloat16* hp = ychi + r * CAT_N + colbase;
        __nv_bfloat16* lp = yclo + r * CAT_N + colbase;
        store_hilo2(o[i][0] * inv, o[i][1] * inv, hp, lp);
        store_hilo2(o[i][2] * inv, o[i][3] * inv, hp + 2, lp + 2);
    }
}

// ---------------------------------------------------------------------------
extern "C" void kernel_launch(void* const* d_in, const int* in_sizes, int n_in,
                              void* d_out, int out_size)
{
    const float* x      = (const float*)d_in[0];   // [8,1024,1024]
    const float* W_attn = (const float*)d_in[1];   // [6144,1024]
    const float* W_proj = (const float*)d_in[2];   // [1024,4096]
    float* out = (float*)d_out;                    // [8,1024,1024]

    float *qkv;
    __nv_bfloat16 *xhi, *xlo, *wahi, *walo, *ychi, *yclo, *wphi, *wplo;
    cudaGetSymbolAddress((void**)&qkv,  g_qkv);
    cudaGetSymbolAddress((void**)&xhi,  g_xhi);
    cudaGetSymbolAddress((void**)&xlo,  g_xlo);
    cudaGetSymbolAddress((void**)&wahi, g_wahi);
    cudaGetSymbolAddress((void**)&walo, g_walo);
    cudaGetSymbolAddress((void**)&ychi, g_ychi);
    cudaGetSymbolAddress((void**)&yclo, g_yclo);
    cudaGetSymbolAddress((void**)&wphi, g_wphi);
    cudaGetSymbolAddress((void**)&wplo, g_wplo);

    cudaFuncSetAttribute(gemm_bf16x3,
                         cudaFuncAttributeMaxDynamicSharedMemorySize, GEMM_SMEM);
    cudaFuncSetAttribute(attn_kernel,
                         cudaFuncAttributeMaxDynamicSharedMemorySize, ATT_SMEM_BYTES);

    // 0) hi/lo conversions for GEMM operand weights + x
    {
        size_t n4 = (size_t)MROWS * CEMB / 4;
        cvt_hilo<<<(unsigned)((n4 + 255) / 256), 256>>>(x, xhi, xlo, n4);
        n4 = (size_t)QKV_N * CEMB / 4;
        cvt_hilo<<<(unsigned)((n4 + 255) / 256), 256>>>(W_attn, wahi, walo, n4);
        n4 = (size_t)CEMB * CAT_N / 4;
        cvt_hilo<<<(unsigned)((n4 + 255) / 256), 256>>>(W_proj, wphi, wplo, n4);
    }

    // 1) qkv = x @ W_attn^T  (mma.sync bf16, 3-pass)
    {
        dim3 grid(QKV_N / 128, MROWS / 128);
        gemm_bf16x3<<<grid, 256, GEMM_SMEM>>>(xhi, xlo, wahi, walo, qkv, QKV_N, CEMB);
    }

    // 2) flash attention per (b,h,g) — writes ychi/yclo directly
    {
        dim3 grid(SEQ / 128, BATCH * NHEAD * NQS);
        attn_kernel<<<grid, 256, ATT_SMEM_BYTES>>>(qkv, ychi, yclo);
    }

    // 3) out = ycat @ W_proj^T  (mma.sync bf16, 3-pass)
    {
        dim3 grid(CEMB / 128, MROWS / 128);
        gemm_bf16x3<<<grid, 256, GEMM_SMEM>>>(ychi, yclo, wphi, wplo, out, CEMB, CAT_N);
    }
}